// round 13
// baseline (speedup 1.0000x reference)
#include <cuda_runtime.h>
#include <cuda_fp16.h>
#include <cstdint>
#include <math.h>

// ---------------- problem constants ----------------
#define DIMC   256
#define SPAT   4096
#define NHEAD  8
#define HDIM   32
#define HIDM   53
#define MAXB   16

// ---------------- device scratch ----------------
__device__ float g_bb[MAXB * 512];                         // adjusted bias [fc1;fcv]
__device__ float g_pool[MAXB * DIMC * 256];                // 16x16 pooled x (avg 4x4)
__device__ __half g_w1hi[512 * DIMC], g_w1lo[512 * DIMC];  // [fc1;fcv] fp16 split
__device__ __half g_xthi[(size_t)MAXB * SPAT * DIMC];      // X^T [b][s][k] fp16 split
__device__ __half g_xtlo[(size_t)MAXB * SPAT * DIMC];
__device__ float g_cns[512 * 128];                         // normalized centers
__device__ float g_vcs[512 * 128];                         // value centers
__device__ float g_sim[(size_t)MAXB * 32 * 1024];          // per-(b,h,win) token sim
__device__ unsigned char g_mstar[(size_t)MAXB * 32 * 1024];
__device__ float g_t[(size_t)MAXB * 4 * 8 * 4 * 256];      // [b][win][h][m][c]
__device__ float g_y[512 * 1024];                          // W2 . outm

// ---------------- PTX helpers ----------------
__device__ __forceinline__ uint32_t smem_u32(const void* p) {
    uint32_t a;
    asm("{ .reg .u64 t; cvta.to.shared.u64 t, %1; cvt.u32.u64 %0, t; }" : "=r"(a) : "l"(p));
    return a;
}
__device__ __forceinline__ void cp_async16(uint32_t s, const void* g) {
    asm volatile("cp.async.cg.shared.global [%0], [%1], 16;" :: "r"(s), "l"(g));
}
#define CP_COMMIT() asm volatile("cp.async.commit_group;" ::: "memory")
#define CP_WAIT(n)  asm volatile("cp.async.wait_group %0;" :: "n"(n) : "memory")

__device__ __forceinline__ void ldsm4(uint32_t* r, uint32_t a) {
    asm volatile("ldmatrix.sync.aligned.m8n8.x4.shared.b16 {%0,%1,%2,%3}, [%4];"
        : "=r"(r[0]), "=r"(r[1]), "=r"(r[2]), "=r"(r[3]) : "r"(a));
}
__device__ __forceinline__ void mma_f16(float* d, const uint32_t* a, const uint32_t* b) {
    asm volatile("mma.sync.aligned.m16n8k16.row.col.f32.f16.f16.f32 "
        "{%0,%1,%2,%3}, {%4,%5,%6,%7}, {%8,%9}, {%0,%1,%2,%3};"
        : "+f"(d[0]), "+f"(d[1]), "+f"(d[2]), "+f"(d[3])
        : "r"(a[0]), "r"(a[1]), "r"(a[2]), "r"(a[3]), "r"(b[0]), "r"(b[1]));
}
__device__ __forceinline__ void hsplit(float v, __half& h, __half& l) {
    h = __float2half_rn(v);
    l = __float2half_rn(v - __half2float(h));
}
// smem tile: rows x 32 f16 (64B/row), 16B-chunk XOR swizzle
__device__ __forceinline__ uint32_t sw_off(int row, int chunk) {
    return (uint32_t)(row * 64 + ((chunk ^ ((row >> 1) & 3)) << 4));
}

// ---------------- kernel 0: fused x reader: transpose+split AND 4x4 pool ----------------
__global__ __launch_bounds__(256)
void convxp_kernel(const float* __restrict__ x) {
    __shared__ float sbuf[32][257];
    const int rg = blockIdx.x;            // 0..15
    const int cgp = blockIdx.y;           // 0..7
    const int b = blockIdx.z;
    const int tid = threadIdx.x;

#pragma unroll
    for (int ci = 0; ci < 32; ci++)
        sbuf[ci][tid] = x[((size_t)(b * DIMC + cgp * 32 + ci)) * SPAT + rg * 256 + tid];
    __syncthreads();

    {
        int s = rg * 256 + tid;
        size_t o = ((size_t)b * SPAT + s) * DIMC + cgp * 32;
        __half hv[32], lv[32];
#pragma unroll
        for (int ci = 0; ci < 32; ci++)
            hsplit(sbuf[ci][tid], hv[ci], lv[ci]);
        uint4* ph = reinterpret_cast<uint4*>(g_xthi + o);
        uint4* pl = reinterpret_cast<uint4*>(g_xtlo + o);
#pragma unroll
        for (int q = 0; q < 4; q++) {
            ph[q] = *reinterpret_cast<uint4*>(&hv[q * 8]);
            pl[q] = *reinterpret_cast<uint4*>(&lv[q * 8]);
        }
    }
    {
        int ci = tid >> 3;
        int pc0 = (tid & 7) * 2;
#pragma unroll
        for (int dp = 0; dp < 2; dp++) {
            int pcol = pc0 + dp;
            float s = 0.f;
#pragma unroll
            for (int r = 0; r < 4; r++)
#pragma unroll
                for (int u = 0; u < 4; u++)
                    s += sbuf[ci][r * 64 + pcol * 4 + u];
            g_pool[((size_t)(b * DIMC + cgp * 32 + ci)) * 256 + rg * 16 + pcol] = s * (1.f / 16.f);
        }
    }
}

// ---------------- kernel 1: fused mean + adjusted bias + weight split ----------------
// Blocks [0,B): per-batch mean + bias; blocks [B, B+512): fp16 weight split.
__global__ __launch_bounds__(256)
void biasmeanw_kernel(const float* __restrict__ w1, const float* __restrict__ b1,
                      const float* __restrict__ wv, const float* __restrict__ bv,
                      const float* __restrict__ scaler, int B) {
    const int tid = threadIdx.x, lane = tid & 31, warp = tid >> 5;
    if ((int)blockIdx.x >= B) {
        int i = ((int)blockIdx.x - B) * 256 + tid;
        if (i < 65536) hsplit(w1[i], g_w1hi[i], g_w1lo[i]);
        else hsplit(wv[i - 65536], g_w1hi[i], g_w1lo[i]);
        return;
    }
    const int b = blockIdx.x;
    __shared__ float mean_s[256], scl[256];
    scl[tid] = scaler[tid];
    for (int j = 0; j < 32; j++) {
        int c = warp * 32 + j;
        const float* p = g_pool + ((size_t)(b * DIMC + c)) * 256;
        float s = 0.f;
#pragma unroll
        for (int i = 0; i < 8; i++) s += p[lane + i * 32];
        for (int o = 16; o; o >>= 1) s += __shfl_down_sync(0xffffffffu, s, o);
        if (lane == 0) mean_s[c] = s * (1.f / 256.f);
    }
    __syncthreads();
    {
        const float* w = w1 + (size_t)tid * DIMC;
        float s = 0.f;
#pragma unroll 8
        for (int c = 0; c < DIMC; c++) s += w[c] * scl[c] * mean_s[c];
        g_bb[b * 512 + tid] = b1[tid] + s;
    }
    {
        const float* w = wv + (size_t)tid * DIMC;
        float s = 0.f;
#pragma unroll 8
        for (int c = 0; c < DIMC; c++) s += w[c] * scl[c] * mean_s[c];
        g_bb[b * 512 + 256 + tid] = bv[tid] + s;
    }
}

// ---------------- kernel 2: mega centers: per-window pooled conv (HMMA) + MLP ----------------
// Block = (b,h,win). Computes pxv rows (x-head 32 + v-head 32) x 64 window positions
// via fp16-split HMMA (A = W rows from g_w1hi/lo; B = pooled x converted in-kernel),
// then the original MLP centers pipeline.
#define CM_SMEM 196608
__global__ __launch_bounds__(256)
void centers_kernel(const float* __restrict__ off_w1, const float* __restrict__ off_b1,
                    const float* __restrict__ off_w2, const float* __restrict__ off_b2) {
    extern __shared__ __align__(1024) char dsm[];
    const int tid = threadIdx.x, lane = tid & 31, warp = tid >> 5;
    const int bbk = blockIdx.x;           // b*32 + h*4 + win
    const int b = bbk >> 5;
    const int h = (bbk >> 2) & 7;
    const int fi = (bbk >> 1) & 1;
    const int fj = bbk & 1;

    __shared__ float b1s[HIDM], b2s[HDIM];
    __shared__ float ctrs[128], vcs[128], cavg[128];
    __shared__ float cnorm[4];

    const uint32_t smb = smem_u32(dsm);
    // regions (bytes): Ahi [0,32768) Alo [32768,65536) Bhi [65536,98304) Blo [98304,131072)
    //                  pool stage [131072, 196608)
    float* poolst = (float*)(dsm + 131072);   // [c][p] 256x64

    // A tiles via cp.async: rows 0..31 = fc1 head rows, 32..63 = fcv head rows
    for (int i = tid; i < 2048; i += 256) {
        int kc = i >> 8, r = (i >> 2) & 63, c = i & 3;
        int R = (r < 32) ? (h * HDIM + r) : (256 + h * HDIM + (r - 32));
        cp_async16(smb + kc * 4096 + sw_off(r, c),
                   g_w1hi + (size_t)R * DIMC + kc * 32 + c * 8);
        cp_async16(smb + 32768 + kc * 4096 + sw_off(r, c),
                   g_w1lo + (size_t)R * DIMC + kc * 32 + c * 8);
    }
    CP_COMMIT();
    // pool tile (fp32), window positions
    for (int i = tid; i < 16384; i += 256) {
        int c = i >> 6, p = i & 63, pi = p >> 3, pj = p & 7;
        poolst[i] = g_pool[((size_t)(b * DIMC + c)) * 256 + (fi * 8 + pi) * 16 + fj * 8 + pj];
    }
    if (tid < HIDM) b1s[tid] = off_b1[tid];
    if (tid < HDIM) b2s[tid] = off_b2[tid];
    __syncthreads();
    // convert pool -> Bhi/Blo swizzled fp16 (row = position p, k = channel c)
    for (int i = tid; i < 16384; i += 256) {
        int c = i >> 6, p = i & 63;
        __half hh, ll;
        hsplit(poolst[i], hh, ll);
        int kc = c >> 5, kk = c & 31;
        uint32_t off = (uint32_t)(kc * 4096) + sw_off(p, kk >> 3) + (kk & 7) * 2;
        *((__half*)(dsm + 65536 + off)) = hh;
        *((__half*)(dsm + 98304 + off)) = ll;
    }
    CP_WAIT(0);
    __syncthreads();

    // MMA: 8 warps, tile 32(m) x 16(n) each
    const int wm = (warp >> 2) * 32, wn = (warp & 3) * 16;
    const int rl = lane & 7, sel = lane >> 3;
    float acc[2][2][4];
#pragma unroll
    for (int i = 0; i < 2; i++)
#pragma unroll
        for (int j = 0; j < 2; j++)
#pragma unroll
            for (int k = 0; k < 4; k++) acc[i][j][k] = 0.f;

#pragma unroll
    for (int kc = 0; kc < 8; kc++) {
        uint32_t ab = smb + kc * 4096;
        uint32_t bbx = smb + 65536 + kc * 4096;
#pragma unroll
        for (int ks = 0; ks < 2; ks++) {
            uint32_t ahi[2][4], alo[2][4];
#pragma unroll
            for (int mt = 0; mt < 2; mt++) {
                int row = wm + mt * 16 + (sel & 1) * 8 + rl;
                int ch = ks * 2 + (sel >> 1);
                uint32_t o = sw_off(row, ch);
                ldsm4(ahi[mt], ab + o);
                ldsm4(alo[mt], ab + 32768 + o);
            }
            uint32_t bhi[2][2], blo[2][2];
            {
                int row = wn + (sel >> 1) * 8 + rl;
                int ch = ks * 2 + (sel & 1);
                uint32_t o = sw_off(row, ch);
                uint32_t r4[4];
                ldsm4(r4, bbx + o);
                bhi[0][0] = r4[0]; bhi[0][1] = r4[1];
                bhi[1][0] = r4[2]; bhi[1][1] = r4[3];
                ldsm4(r4, bbx + 32768 + o);
                blo[0][0] = r4[0]; blo[0][1] = r4[1];
                blo[1][0] = r4[2]; blo[1][1] = r4[3];
            }
#pragma unroll
            for (int mt = 0; mt < 2; mt++)
#pragma unroll
                for (int nt = 0; nt < 2; nt++) {
                    mma_f16(acc[mt][nt], ahi[mt], bhi[nt]);
                    mma_f16(acc[mt][nt], ahi[mt], blo[nt]);
                    mma_f16(acc[mt][nt], alo[mt], bhi[nt]);
                }
        }
    }
    __syncthreads();    // A/B/pool regions dead from here

    // axv[r][p] = pxv + bias (alias over Ahi region)
    float* axv = (float*)dsm;    // [64][64]
    {
        int g = lane >> 2, tig = lane & 3;
#pragma unroll
        for (int mt = 0; mt < 2; mt++) {
            int r0 = wm + mt * 16 + g;
            int R0 = (r0 < 32) ? (h * HDIM + r0) : (256 + h * HDIM + (r0 - 32));
            int r1 = r0 + 8;
            int R1 = (r1 < 32) ? (h * HDIM + r1) : (256 + h * HDIM + (r1 - 32));
            float bb0 = g_bb[b * 512 + R0];
            float bb1 = g_bb[b * 512 + R1];
#pragma unroll
            for (int nt = 0; nt < 2; nt++) {
                int col = wn + nt * 8 + 2 * tig;
                axv[r0 * 64 + col]     = acc[mt][nt][0] + bb0;
                axv[r0 * 64 + col + 1] = acc[mt][nt][1] + bb0;
                axv[r1 * 64 + col]     = acc[mt][nt][2] + bb1;
                axv[r1 * 64 + col + 1] = acc[mt][nt][3] + bb1;
            }
        }
    }
    // MLP buffers aliased after axv (byte 16384+)
    float* a8   = (float*)dsm + 4096;    // 2048 floats
    float* hbuf = (float*)dsm + 6144;    // HIDM*64 = 3392
    float* w1s  = (float*)dsm + 9536;    // 1696
    float* w2s  = (float*)dsm + 11232;   // 1696
    for (int i = tid; i < HIDM * HDIM; i += 256) { w1s[i] = off_w1[i]; w2s[i] = off_w2[i]; }

    for (int pass = 0; pass < 2; pass++) {
        float* dst = (pass == 0) ? vcs : ctrs;
        __syncthreads();
        // slice: pass0 = value rows 32..63, pass1 = x rows 0..31
        for (int i = tid; i < 2048; i += 256) {
            int c = i >> 6, p = i & 63;
            a8[i] = axv[((pass == 0 ? 32 : 0) + c) * 64 + p];
        }
        __syncthreads();
        if (tid < 128) {
            int m = tid >> 5, c = tid & 31, qi = m >> 1, qj = m & 1;
            float s = 0.f;
#pragma unroll
            for (int u = 0; u < 4; u++)
#pragma unroll
                for (int v2 = 0; v2 < 4; v2++)
                    s += a8[c * 64 + (qi * 4 + u) * 8 + qj * 4 + v2];
            cavg[tid] = s * (1.f / 16.f);
        }
        for (int eh = tid; eh < HIDM * 64; eh += 256) {
            int j = eh >> 6, p = eh & 63;
            float s = b1s[j];
#pragma unroll
            for (int c = 0; c < HDIM; c++) s += w1s[j * HDIM + c] * a8[c * 64 + p];
            hbuf[eh] = 0.5f * s * (1.f + erff(s * 0.70710678118654752440f));
        }
        __syncthreads();
        for (int eo = tid; eo < 2048; eo += 256) {
            int c = eo >> 6, p = eo & 63;
            float s = b2s[c];
#pragma unroll
            for (int j = 0; j < HIDM; j++) s += w2s[c * HIDM + j] * hbuf[j * 64 + p];
            a8[eo] = s;
        }
        __syncthreads();
        if (tid < 128) {
            int m = tid >> 5, c = tid & 31, qi = m >> 1, qj = m & 1;
            float mx = -INFINITY;
#pragma unroll
            for (int u = 0; u < 4; u++)
#pragma unroll
                for (int v2 = 0; v2 < 4; v2++)
                    mx = fmaxf(mx, a8[c * 64 + (qi * 4 + u) * 8 + qj * 4 + v2]);
            dst[tid] = cavg[tid] + mx;
        }
        __syncthreads();
    }

    if (tid < 4) {
        float s = 0.f;
#pragma unroll
        for (int c = 0; c < HDIM; c++) { float v = ctrs[tid * 32 + c]; s += v * v; }
        cnorm[tid] = fmaxf(sqrtf(s), 1e-12f);
    }
    __syncthreads();
    if (tid < 128) {
        g_cns[(size_t)bbk * 128 + tid] = ctrs[tid] / cnorm[tid >> 5];
        g_vcs[(size_t)bbk * 128 + tid] = vcs[tid];
    }
}

// ---------------- kernel 3: main fused GEMM (fc1) + sim/argmax epilogue ----------------
// 3-stage cp.async pipeline, single sync per iteration, 2 CTAs/SM.
__global__ __launch_bounds__(256, 2)
void gemm_sim_kernel(const __half* __restrict__ whi, const __half* __restrict__ wlo,
                     const __half* __restrict__ xhi, const __half* __restrict__ xlo,
                     const float* __restrict__ alphaP, const float* __restrict__ betaP) {
    extern __shared__ __align__(1024) char sm[];   // 3 x 32KB stages; epilogue reuse
    __shared__ float cns_s[4][2][4][32];
    const int tid = threadIdx.x, lane = tid & 31, warp = tid >> 5;
    const int b = blockIdx.z, n0 = blockIdx.x * 128, m0 = blockIdx.y * 128;
    const int wm = (warp >> 2) * 64, wn = (warp & 3) * 32;

    const __half* srcs[4] = {
        whi + (size_t)m0 * DIMC, wlo + (size_t)m0 * DIMC,
        xhi + ((size_t)b * SPAT + n0) * DIMC, xlo + ((size_t)b * SPAT + n0) * DIMC };
    const uint32_t smb = smem_u32(sm);

    float acc[4][4][4];
#pragma unroll
    for (int i = 0; i < 4; i++)
#pragma unroll
        for (int j = 0; j < 4; j++)
#pragma unroll
            for (int k = 0; k < 4; k++) acc[i][j][k] = 0.f;

    auto load_stage = [&](int stage, int kc) {
#pragma unroll
        for (int t = 0; t < 4; t++) {
#pragma unroll
            for (int i = 0; i < 2; i++) {
                int chunkid = tid + 256 * i;
                int row = chunkid >> 2, c = chunkid & 3;
                cp_async16(smb + stage * 32768 + t * 8192 + sw_off(row, c),
                           srcs[t] + (size_t)row * DIMC + kc * 32 + c * 8);
            }
        }
        CP_COMMIT();
    };
    const int rl = lane & 7, sel = lane >> 3;

    load_stage(0, 0);
    load_stage(1, 1);
    for (int kc = 0; kc < 8; kc++) {
        if (kc < 7) { CP_WAIT(1); } else { CP_WAIT(0); }
        __syncthreads();
        if (kc + 2 < 8) load_stage((kc + 2) % 3, kc + 2);
        const uint32_t base = smb + (kc % 3) * 32768;
#pragma unroll
        for (int ks = 0; ks < 2; ks++) {
            uint32_t ahi[4][4], alo[4][4];
#pragma unroll
            for (int mt = 0; mt < 4; mt++) {
                int row = wm + mt * 16 + (sel & 1) * 8 + rl;
                int ch = ks * 2 + (sel >> 1);
                uint32_t o = sw_off(row, ch);
                ldsm4(ahi[mt], base + o);
                ldsm4(alo[mt], base + 8192 + o);
            }
            uint32_t bhi[4][2], blo[4][2];
#pragma unroll
            for (int p = 0; p < 2; p++) {
                int row = wn + p * 16 + (sel >> 1) * 8 + rl;
                int ch = ks * 2 + (sel & 1);
                uint32_t o = sw_off(row, ch);
                uint32_t r4[4];
                ldsm4(r4, base + 16384 + o);
                bhi[2 * p][0] = r4[0]; bhi[2 * p][1] = r4[1];
                bhi[2 * p + 1][0] = r4[2]; bhi[2 * p + 1][1] = r4[3];
                ldsm4(r4, base + 24576 + o);
                blo[2 * p][0] = r4[0]; blo[2 * p][1] = r4[1];
                blo[2 * p + 1][0] = r4[2]; blo[2 * p + 1][1] = r4[3];
            }
#pragma unroll
            for (int mt = 0; mt < 4; mt++)
#pragma unroll
                for (int nt = 0; nt < 4; nt++) {
                    mma_f16(acc[mt][nt], ahi[mt], bhi[nt]);
                    mma_f16(acc[mt][nt], ahi[mt], blo[nt]);
                    mma_f16(acc[mt][nt], alo[mt], bhi[nt]);
                }
        }
    }
    __syncthreads();    // all warps done with stage buffers before epilogue reuse

    // ---- epilogue: x1 tile -> smem, then per-token norms + sims + argmax ----
    const int h0 = m0 >> 5;
    const int fi = (n0 >= 2048) ? 1 : 0;
    float* epi = (float*)sm;                // [128 rows][132 stride]
    {
        const int g = lane >> 2, tig = lane & 3;
#pragma unroll
        for (int mt = 0; mt < 4; mt++) {
            int lr0 = wm + mt * 16 + g;
            float b0v = g_bb[b * 512 + m0 + lr0];
            float b1v = g_bb[b * 512 + m0 + lr0 + 8];
#pragma unroll
            for (int nt = 0; nt < 4; nt++) {
                int col = wn + nt * 8 + 2 * tig;
                epi[lr0 * 132 + col]           = acc[mt][nt][0] + b0v;
                epi[lr0 * 132 + col + 1]       = acc[mt][nt][1] + b0v;
                epi[(lr0 + 8) * 132 + col]     = acc[mt][nt][2] + b1v;
                epi[(lr0 + 8) * 132 + col + 1] = acc[mt][nt][3] + b1v;
            }
        }
    }
    for (int i = tid; i < 1024; i += 256) {
        int hl = i >> 8, fjj = (i >> 7) & 1, m = (i >> 5) & 3, d = i & 31;
        int bbk = b * 32 + (h0 + hl) * 4 + fi * 2 + fjj;
        cns_s[hl][fjj][m][d] = g_cns[(size_t)bbk * 128 + m * 32 + d];
    }
    __syncthreads();

    const float alpha = alphaP[0], beta = betaP[0];
    const int hl = tid >> 6, tp = tid & 63;
#pragma unroll
    for (int rep = 0; rep < 2; rep++) {
        int tk = tp * 2 + rep;
        int s = n0 + tk;
        int hj = s & 63, fj = hj >> 5;
        int nw = ((s >> 6) & 31) * 32 + (hj & 31);
        float nrm = 0.f, dm[4] = {0.f, 0.f, 0.f, 0.f};
#pragma unroll
        for (int d = 0; d < 32; d++) {
            float v = epi[(hl * 32 + d) * 132 + tk];
            nrm += v * v;
#pragma unroll
            for (int m = 0; m < 4; m++) dm[m] += cns_s[hl][fj][m][d] * v;
        }
        float inv = 1.f / fmaxf(sqrtf(nrm), 1e-12f);
        float best = -1.f; int bm = 0;
#pragma unroll
        for (int m = 0; m < 4; m++) {
            float sg = 1.f / (1.f + expf(-(beta + alpha * dm[m] * inv)));
            if (sg > best) { best = sg; bm = m; }
        }
        size_t idx = ((size_t)(b * 8 + h0 + hl) * 4 + fi * 2 + fj) * 1024 + nw;
        g_sim[idx] = best;
        g_mstar[idx] = (unsigned char)bm;
    }
}

// ---------------- kernel 4: t = sum sim*x  (grid: 4 cgroups x 4 win x B) ----------------
__global__ __launch_bounds__(256)
void taccum_kernel() {
    const int cg = blockIdx.x;
    const int win = blockIdx.y;
    const int b = blockIdx.z;
    const int fi = win >> 1, fj = win & 1;
    const int tid = threadIdx.x;
    const int cp = tid & 31;
    const int h = tid >> 5;

    __shared__ float stage[64][64];
    __shared__ float ws[8][4][64];

    float2 acc[4];
#pragma unroll
    for (int m = 0; m < 4; m++) acc[m] = make_float2(0.f, 0.f);

    for (int chunk = 0; chunk < 16; chunk++) {
#pragma unroll
        for (int it = 0; it < 8; it++) {
            int i = it * 256 + tid;
            int t = i >> 5, cq = i & 31;
            int n = chunk * 64 + t;
            int s = (fi * 32 + (n >> 5)) * 64 + fj * 32 + (n & 31);
            size_t off2 = (((size_t)b * SPAT + s) * DIMC + cg * 64) / 2 + cq;
            float2 hf = __half22float2(reinterpret_cast<const __half2*>(g_xthi)[off2]);
            float2 lf = __half22float2(reinterpret_cast<const __half2*>(g_xtlo)[off2]);
            *reinterpret_cast<float2*>(&stage[t][2 * cq]) =
                make_float2(hf.x + lf.x, hf.y + lf.y);
        }
#pragma unroll
        for (int it = 0; it < 8; it++) {
            int i = it * 256 + tid;
            int hh = i >> 8, mm = (i >> 6) & 3, t = i & 63;
            size_t sb = ((size_t)(b * 8 + hh) * 4 + win) * 1024 + chunk * 64 + t;
            ws[hh][mm][t] = (g_mstar[sb] == (unsigned char)mm) ? g_sim[sb] : 0.f;
        }
        __syncthreads();
#pragma unroll 4
        for (int t = 0; t < 64; t++) {
            float2 xv = *reinterpret_cast<const float2*>(&stage[t][2 * cp]);
#pragma unroll
            for (int m = 0; m < 4; m++) {
                float w = ws[h][m][t];
                acc[m].x += w * xv.x;
                acc[m].y += w * xv.y;
            }
        }
        __syncthreads();
    }
#pragma unroll
    for (int m = 0; m < 4; m++) {
        size_t o = (((size_t)(b * 4 + win) * 8 + h) * 4 + m) * 256 + cg * 64 + 2 * cp;
        *reinterpret_cast<float2*>(&g_t[o]) = acc[m];
    }
}

// ---------------- kernel 5: outm + y fused ----------------
__global__ __launch_bounds__(256)
void outm_y_kernel(const float* __restrict__ wv, const float* __restrict__ w2) {
    const int bbk = blockIdx.x;
    const int b = bbk >> 5;
    const int h = (bbk >> 2) & 7;
    const int win = bbk & 3;
    const int tid = threadIdx.x, lane = tid & 31, warp = tid >> 5;

    __shared__ float t_s[4][256];
    __shared__ float wbuf[8448];
    __shared__ float sigs[4], cnts[4];
    __shared__ float outm_s[128];

    for (int i = tid; i < 1024; i += 256)
        t_s[i >> 8][i & 255] = g_t[(((size_t)(b * 4 + win) * 8 + h) * 4 + (i >> 8)) * 256 + (i & 255)];
    if (warp < 4) {
        float s = 0.f, c = 0.f;
        for (int n = lane; n < 1024; n += 32) {
            size_t sb = ((size_t)(b * 8 + h) * 4 + win) * 1024 + n;
            if (g_mstar[sb] == (unsigned char)warp) { s += g_sim[sb]; c += 1.f; }
        }
        for (int o = 16; o; o >>= 1) {
            s += __shfl_down_sync(0xffffffffu, s, o);
            c += __shfl_down_sync(0xffffffffu, c, o);
        }
        if (lane == 0) { sigs[warp] = s; cnts[warp] = c; }
    }
    for (int i = tid; i < 32 * 256; i += 256) {
        int r = i >> 8, c = i & 255;
        wbuf[r * 257 + c] = wv[(size_t)(h * HDIM + r) * DIMC + c];
    }
    __syncthreads();

    if (tid < 128) {
        int m = tid >> 5, d = tid & 31;
        float s = 0.f;
#pragma unroll 8
        for (int c = 0; c < DIMC; c++) s += wbuf[d * 257 + c] * t_s[m][c];
        float bbv = g_bb[b * 512 + 256 + h * HDIM + d];
        float vc = g_vcs[(size_t)bbk * 128 + m * 32 + d];
        outm_s[tid] = (s + sigs[m] * bbv + vc) / (cnts[m] + 1.f);
    }
    __syncthreads();
    for (int i = tid; i < 256 * 32; i += 256) {
        int o = i >> 5, d = i & 31;
        wbuf[o * 33 + d] = w2[(size_t)o * DIMC + h * HDIM + d];
    }
    __syncthreads();
    {
        int o = tid;
        float yv[4] = {0.f, 0.f, 0.f, 0.f};
#pragma unroll
        for (int d = 0; d < HDIM; d++) {
            float w = wbuf[o * 33 + d];
#pragma unroll
            for (int m = 0; m < 4; m++) yv[m] += w * outm_s[m * 32 + d];
        }
#pragma unroll
        for (int m = 0; m < 4; m++)
            g_y[(size_t)bbk * 1024 + m * 256 + o] = yv[m];
    }
}

// ---------------- kernel 6: combine -> final output ----------------
__global__ __launch_bounds__(256)
void combine_kernel(const float* __restrict__ b2, float* __restrict__ out) {
    const int o0 = blockIdx.x * 32;
    const int win = blockIdx.y;
    const int batch = blockIdx.z;
    const int fi = win >> 1, fj = win & 1;
    const int tid = threadIdx.x, lane = tid & 31, warp = tid >> 5;

    __shared__ float ys[8][4][33];
    __shared__ float b2s[32];

    for (int i = tid; i < 8 * 4 * 32; i += 256) {
        int h = i >> 7, m = (i >> 5) & 3, o = i & 31;
        ys[h][m][o] = g_y[((size_t)(batch * 8 + h) * 4 + win) * 1024 + m * 256 + o0 + o];
    }
    if (tid < 32) b2s[tid] = b2[o0 + tid];
    __syncthreads();

#pragma unroll
    for (int r = 0; r < 4; r++) {
        int wi = warp * 4 + r;
        int n = wi * 32 + lane;
        float simr[8];
        int mr[8];
#pragma unroll
        for (int h = 0; h < 8; h++) {
            size_t sb = ((size_t)(batch * 8 + h) * 4 + win) * 1024 + n;
            simr[h] = g_sim[sb];
            mr[h] = g_mstar[sb];
        }
        int s = (fi * 32 + wi) * 64 + fj * 32 + lane;
        float* op = out + ((size_t)batch * DIMC + o0) * SPAT + s;
#pragma unroll
        for (int o = 0; o < 32; o++) {
            float acc = b2s[o];
#pragma unroll
            for (int h = 0; h < 8; h++) acc += simr[h] * ys[h][mr[h]][o];
            op[(size_t)o * SPAT] = acc;
        }
    }
}

// ---------------- launcher ----------------
extern "C" void kernel_launch(void* const* d_in, const int* in_sizes, int n_in,
                              void* d_out, int out_size) {
    const float* x      = (const float*)d_in[0];
    const float* scaler = (const float*)d_in[1];
    const float* w_fc1  = (const float*)d_in[2];
    const float* b_fc1  = (const float*)d_in[3];
    const float* w_fcv  = (const float*)d_in[4];
    const float* b_fcv  = (const float*)d_in[5];
    const float* w_fc2  = (const float*)d_in[6];
    const float* b_fc2  = (const float*)d_in[7];
    const float* alpha  = (const float*)d_in[8];
    const float* beta   = (const float*)d_in[9];
    const float* off_w1 = (const float*)d_in[10];
    const float* off_b1 = (const float*)d_in[11];
    const float* off_w2 = (const float*)d_in[12];
    const float* off_b2 = (const float*)d_in[13];
    float* out = (float*)d_out;

    int B = in_sizes[0] / (DIMC * SPAT);
    if (B > MAXB) B = MAXB;

    __half *p_w1h, *p_w1l, *p_xth, *p_xtl;
    cudaGetSymbolAddress((void**)&p_w1h, g_w1hi);
    cudaGetSymbolAddress((void**)&p_w1l, g_w1lo);
    cudaGetSymbolAddress((void**)&p_xth, g_xthi);
    cudaGetSymbolAddress((void**)&p_xtl, g_xtlo);

    static bool attr_set = false;
    if (!attr_set) {
        cudaFuncSetAttribute(gemm_sim_kernel, cudaFuncAttributeMaxDynamicSharedMemorySize, 98304);
        cudaFuncSetAttribute(centers_kernel,  cudaFuncAttributeMaxDynamicSharedMemorySize, CM_SMEM);
        attr_set = true;
    }

    // 0. fused x reader: transpose+split + pooled
    {
        dim3 g(16, 8, B);
        convxp_kernel<<<g, 256>>>(x);
    }
    // 1. fused mean + adjusted bias + fp16 weight split
    biasmeanw_kernel<<<B + 512, 256>>>(w_fc1, b_fc1, w_fcv, b_fcv, scaler, B);
    // 2. mega centers: per-window pooled conv (HMMA) + MLP + l2norm
    centers_kernel<<<B * 32, 256, CM_SMEM>>>(off_w1, off_b1, off_w2, off_b2);
    // 3. main fused GEMM + sim/argmax  (launch index 3 -> ncu profiled)
    {
        dim3 grid(SPAT / 128, 256 / 128, B);
        gemm_sim_kernel<<<grid, 256, 98304>>>(p_w1h, p_w1l, p_xth, p_xtl, alpha, beta);
    }
    // 4. t = sum sim*x per cluster
    {
        dim3 grid(4, 4, B);
        taccum_kernel<<<grid, 256>>>();
    }
    // 5. outm + y fused
    outm_y_kernel<<<B * 32, 256>>>(w_fcv, w_fc2);
    // 6. combine -> final output
    {
        dim3 grid(8, 4, B);
        combine_kernel<<<grid, 256>>>(b_fc2, out);
    }
}

// round 14
// speedup vs baseline: 1.1315x; 1.1315x over previous
#include <cuda_runtime.h>
#include <cuda_fp16.h>
#include <cstdint>
#include <math.h>

// ---------------- problem constants ----------------
#define DIMC   256
#define SPAT   4096
#define NHEAD  8
#define HDIM   32
#define HIDM   53
#define MAXB   16

// ---------------- device scratch ----------------
__device__ float g_bb[MAXB * 512];                         // adjusted bias [fc1;fcv]
__device__ float g_pool[MAXB * DIMC * 256];                // 16x16 pooled x (avg 4x4)
__device__ __half g_w1hi[512 * DIMC], g_w1lo[512 * DIMC];  // [fc1;fcv] fp16 split
__device__ __half g_xthi[(size_t)MAXB * SPAT * DIMC];      // X^T [b][s][k] fp16 split
__device__ __half g_xtlo[(size_t)MAXB * SPAT * DIMC];
__device__ __half g_pthi[MAXB * 256 * DIMC];               // pooled^T [b][p][k]
__device__ __half g_ptlo[MAXB * 256 * DIMC];
__device__ float g_pxv[MAXB * 512 * 256];                  // pooled fc1+fcv out
__device__ float g_cns[512 * 128];                         // normalized centers
__device__ float g_vcs[512 * 128];                         // value centers
__device__ float g_sim[(size_t)MAXB * 32 * 1024];          // per-(b,h,win) token sim
__device__ unsigned char g_mstar[(size_t)MAXB * 32 * 1024];
__device__ float g_t[(size_t)MAXB * 4 * 8 * 4 * 256];      // [b][win][h][m][c]
__device__ float g_y[512 * 1024];                          // W2 . outm

// ---------------- PTX helpers ----------------
__device__ __forceinline__ uint32_t smem_u32(const void* p) {
    uint32_t a;
    asm("{ .reg .u64 t; cvta.to.shared.u64 t, %1; cvt.u32.u64 %0, t; }" : "=r"(a) : "l"(p));
    return a;
}
__device__ __forceinline__ void cp_async16(uint32_t s, const void* g) {
    asm volatile("cp.async.cg.shared.global [%0], [%1], 16;" :: "r"(s), "l"(g));
}
#define CP_COMMIT() asm volatile("cp.async.commit_group;" ::: "memory")
#define CP_WAIT(n)  asm volatile("cp.async.wait_group %0;" :: "n"(n) : "memory")

__device__ __forceinline__ void ldsm4(uint32_t* r, uint32_t a) {
    asm volatile("ldmatrix.sync.aligned.m8n8.x4.shared.b16 {%0,%1,%2,%3}, [%4];"
        : "=r"(r[0]), "=r"(r[1]), "=r"(r[2]), "=r"(r[3]) : "r"(a));
}
__device__ __forceinline__ void mma_f16(float* d, const uint32_t* a, const uint32_t* b) {
    asm volatile("mma.sync.aligned.m16n8k16.row.col.f32.f16.f16.f32 "
        "{%0,%1,%2,%3}, {%4,%5,%6,%7}, {%8,%9}, {%0,%1,%2,%3};"
        : "+f"(d[0]), "+f"(d[1]), "+f"(d[2]), "+f"(d[3])
        : "r"(a[0]), "r"(a[1]), "r"(a[2]), "r"(a[3]), "r"(b[0]), "r"(b[1]));
}
__device__ __forceinline__ void hsplit(float v, __half& h, __half& l) {
    h = __float2half_rn(v);
    l = __float2half_rn(v - __half2float(h));
}
// smem tile: rows x 32 f16 (64B/row), 16B-chunk XOR swizzle
__device__ __forceinline__ uint32_t sw_off(int row, int chunk) {
    return (uint32_t)(row * 64 + ((chunk ^ ((row >> 1) & 3)) << 4));
}

// ---------------- kernel 0: fused x reader: transpose+split AND 4x4 pool ----------------
__global__ __launch_bounds__(256)
void convxp_kernel(const float* __restrict__ x) {
    __shared__ float sbuf[32][257];
    const int rg = blockIdx.x;            // 0..15
    const int cgp = blockIdx.y;           // 0..7
    const int b = blockIdx.z;
    const int tid = threadIdx.x;

#pragma unroll
    for (int ci = 0; ci < 32; ci++)
        sbuf[ci][tid] = x[((size_t)(b * DIMC + cgp * 32 + ci)) * SPAT + rg * 256 + tid];
    __syncthreads();

    {
        int s = rg * 256 + tid;
        size_t o = ((size_t)b * SPAT + s) * DIMC + cgp * 32;
        __half hv[32], lv[32];
#pragma unroll
        for (int ci = 0; ci < 32; ci++)
            hsplit(sbuf[ci][tid], hv[ci], lv[ci]);
        uint4* ph = reinterpret_cast<uint4*>(g_xthi + o);
        uint4* pl = reinterpret_cast<uint4*>(g_xtlo + o);
#pragma unroll
        for (int q = 0; q < 4; q++) {
            ph[q] = *reinterpret_cast<uint4*>(&hv[q * 8]);
            pl[q] = *reinterpret_cast<uint4*>(&lv[q * 8]);
        }
    }
    {
        int ci = tid >> 3;
        int pc0 = (tid & 7) * 2;
#pragma unroll
        for (int dp = 0; dp < 2; dp++) {
            int pcol = pc0 + dp;
            float s = 0.f;
#pragma unroll
            for (int r = 0; r < 4; r++)
#pragma unroll
                for (int u = 0; u < 4; u++)
                    s += sbuf[ci][r * 64 + pcol * 4 + u];
            g_pool[((size_t)(b * DIMC + cgp * 32 + ci)) * 256 + rg * 16 + pcol] = s * (1.f / 16.f);
        }
    }
}

// ---------------- kernel 1: fused mean + adjusted bias + weight split ----------------
__global__ __launch_bounds__(256)
void biasmeanw_kernel(const float* __restrict__ w1, const float* __restrict__ b1,
                      const float* __restrict__ wv, const float* __restrict__ bv,
                      const float* __restrict__ scaler, int B) {
    const int tid = threadIdx.x, lane = tid & 31, warp = tid >> 5;
    if ((int)blockIdx.x >= B) {
        int i = ((int)blockIdx.x - B) * 256 + tid;
        if (i < 65536) hsplit(w1[i], g_w1hi[i], g_w1lo[i]);
        else hsplit(wv[i - 65536], g_w1hi[i], g_w1lo[i]);
        return;
    }
    const int b = blockIdx.x;
    __shared__ float mean_s[256], scl[256];
    scl[tid] = scaler[tid];
    for (int j = 0; j < 32; j++) {
        int c = warp * 32 + j;
        const float* p = g_pool + ((size_t)(b * DIMC + c)) * 256;
        float s = 0.f;
#pragma unroll
        for (int i = 0; i < 8; i++) s += p[lane + i * 32];
        for (int o = 16; o; o >>= 1) s += __shfl_down_sync(0xffffffffu, s, o);
        if (lane == 0) mean_s[c] = s * (1.f / 256.f);
    }
    __syncthreads();
    {
        const float* w = w1 + (size_t)tid * DIMC;
        float s = 0.f;
#pragma unroll 8
        for (int c = 0; c < DIMC; c++) s += w[c] * scl[c] * mean_s[c];
        g_bb[b * 512 + tid] = b1[tid] + s;
    }
    {
        const float* w = wv + (size_t)tid * DIMC;
        float s = 0.f;
#pragma unroll 8
        for (int c = 0; c < DIMC; c++) s += w[c] * scl[c] * mean_s[c];
        g_bb[b * 512 + 256 + tid] = bv[tid] + s;
    }
}

// ---------------- kernel 2: transpose+split pooled -> [b][p][c] hi/lo ----------------
__global__ void convx_kernel(const float* __restrict__ src, __half* __restrict__ dhi,
                             __half* __restrict__ dlo, int S) {
    __shared__ float t[32][33];
    int s0 = blockIdx.x * 32, c0 = blockIdx.y * 32, b = blockIdx.z;
    int tx = threadIdx.x, ty = threadIdx.y;
#pragma unroll
    for (int i = 0; i < 4; i++)
        t[ty + i * 8][tx] = src[((size_t)(b * DIMC + c0 + ty + i * 8)) * S + s0 + tx];
    __syncthreads();
#pragma unroll
    for (int i = 0; i < 4; i++) {
        int s = s0 + ty + i * 8;
        float v = t[tx][ty + i * 8];
        __half h, l;
        hsplit(v, h, l);
        size_t o = ((size_t)b * S + s) * DIMC + c0 + tx;
        dhi[o] = h;
        dlo[o] = l;
    }
}

// ---------------- kernel 3: generic HMMA fp16-split GEMM (pooled conv) ----------------
__global__ __launch_bounds__(256)
void gemm_hmma_kernel(const __half* __restrict__ whi, const __half* __restrict__ wlo,
                      const __half* __restrict__ xhi, const __half* __restrict__ xlo,
                      const float* __restrict__ bias, float* __restrict__ O,
                      int M, int S, int biasPerBatch) {
    extern __shared__ __align__(1024) char sm[];
    const int tid = threadIdx.x, lane = tid & 31, warp = tid >> 5;
    const int b = blockIdx.z, n0 = blockIdx.x * 128, m0 = blockIdx.y * 128;
    const int wm = (warp >> 2) * 64, wn = (warp & 3) * 32;

    const __half* srcs[4] = {
        whi + (size_t)m0 * DIMC, wlo + (size_t)m0 * DIMC,
        xhi + ((size_t)b * S + n0) * DIMC, xlo + ((size_t)b * S + n0) * DIMC };
    const uint32_t smb = smem_u32(sm);

    float acc[4][4][4];
#pragma unroll
    for (int i = 0; i < 4; i++)
#pragma unroll
        for (int j = 0; j < 4; j++)
#pragma unroll
            for (int k = 0; k < 4; k++) acc[i][j][k] = 0.f;

    auto load_stage = [&](int stage, int kc) {
#pragma unroll
        for (int t = 0; t < 4; t++) {
#pragma unroll
            for (int i = 0; i < 2; i++) {
                int chunkid = tid + 256 * i;
                int row = chunkid >> 2, c = chunkid & 3;
                cp_async16(smb + stage * 32768 + t * 8192 + sw_off(row, c),
                           srcs[t] + (size_t)row * DIMC + kc * 32 + c * 8);
            }
        }
        CP_COMMIT();
    };
    const int rl = lane & 7, sel = lane >> 3;

    load_stage(0, 0);
    int stage = 0;
    for (int kc = 0; kc < 8; kc++) {
        if (kc + 1 < 8) { load_stage(stage ^ 1, kc + 1); CP_WAIT(1); }
        else            { CP_WAIT(0); }
        __syncthreads();
        const uint32_t base = smb + stage * 32768;
#pragma unroll
        for (int ks = 0; ks < 2; ks++) {
            uint32_t ahi[4][4], alo[4][4];
#pragma unroll
            for (int mt = 0; mt < 4; mt++) {
                int row = wm + mt * 16 + (sel & 1) * 8 + rl;
                int ch = ks * 2 + (sel >> 1);
                uint32_t o = sw_off(row, ch);
                ldsm4(ahi[mt], base + o);
                ldsm4(alo[mt], base + 8192 + o);
            }
            uint32_t bhi[4][2], blo[4][2];
#pragma unroll
            for (int p = 0; p < 2; p++) {
                int row = wn + p * 16 + (sel >> 1) * 8 + rl;
                int ch = ks * 2 + (sel & 1);
                uint32_t o = sw_off(row, ch);
                uint32_t r4[4];
                ldsm4(r4, base + 16384 + o);
                bhi[2 * p][0] = r4[0]; bhi[2 * p][1] = r4[1];
                bhi[2 * p + 1][0] = r4[2]; bhi[2 * p + 1][1] = r4[3];
                ldsm4(r4, base + 24576 + o);
                blo[2 * p][0] = r4[0]; blo[2 * p][1] = r4[1];
                blo[2 * p + 1][0] = r4[2]; blo[2 * p + 1][1] = r4[3];
            }
#pragma unroll
            for (int mt = 0; mt < 4; mt++)
#pragma unroll
                for (int nt = 0; nt < 4; nt++) {
                    mma_f16(acc[mt][nt], ahi[mt], bhi[nt]);
                    mma_f16(acc[mt][nt], ahi[mt], blo[nt]);
                    mma_f16(acc[mt][nt], alo[mt], bhi[nt]);
                }
        }
        __syncthreads();
        stage ^= 1;
    }
    const int g = lane >> 2, tig = lane & 3;
    const int bofs = biasPerBatch ? b * M : 0;
#pragma unroll
    for (int mt = 0; mt < 4; mt++) {
        int r0 = m0 + wm + mt * 16 + g;
        float b0v = bias[bofs + r0];
        float b1v = bias[bofs + r0 + 8];
        float* orow0 = O + ((size_t)b * M + r0) * S + n0;
        float* orow1 = orow0 + (size_t)8 * S;
#pragma unroll
        for (int nt = 0; nt < 4; nt++) {
            int col = wn + nt * 8 + 2 * tig;
            *reinterpret_cast<float2*>(orow0 + col) =
                make_float2(acc[mt][nt][0] + b0v, acc[mt][nt][1] + b0v);
            *reinterpret_cast<float2*>(orow1 + col) =
                make_float2(acc[mt][nt][2] + b1v, acc[mt][nt][3] + b1v);
        }
    }
}

// ---------------- kernel 4: centers (pooled pipeline -> cns, vcs) ----------------
__global__ __launch_bounds__(256)
void centers_kernel(const float* __restrict__ w1, const float* __restrict__ bb1,
                    const float* __restrict__ w2, const float* __restrict__ bb2) {
    const int tid = threadIdx.x;
    const int bbk = blockIdx.x;           // b*32 + h*4 + win
    const int b = bbk >> 5;
    const int h = (bbk >> 2) & 7;
    const int fi = (bbk >> 1) & 1;
    const int fj = bbk & 1;

    __shared__ float a8[2048];
    __shared__ float hbuf[HIDM * 64];
    __shared__ float w1s[HIDM * HDIM], b1s[HIDM], w2s[HDIM * HIDM], b2s[HDIM];
    __shared__ float ctrs[128], vcs[128], cavg[128];
    __shared__ float cnorm[4];

    for (int i = tid; i < HIDM * HDIM; i += 256) { w1s[i] = w1[i]; w2s[i] = w2[i]; }
    if (tid < HIDM) b1s[tid] = bb1[tid];
    if (tid < HDIM) b2s[tid] = bb2[tid];

    for (int pass = 0; pass < 2; pass++) {
        const int base_row = (pass == 0) ? (256 + h * HDIM) : (h * HDIM);
        float* dst = (pass == 0) ? vcs : ctrs;
        __syncthreads();
#pragma unroll
        for (int rep = 0; rep < 8; rep++) {
            int e = rep * 256 + tid;
            int c = e >> 6, pos = e & 63;
            a8[c * 64 + pos] = g_pxv[((size_t)(b * 512) + base_row + c) * 256
                                     + (fi * 8 + (pos >> 3)) * 16 + fj * 8 + (pos & 7)];
        }
        __syncthreads();
        if (tid < 128) {
            int m = tid >> 5, c = tid & 31, qi = m >> 1, qj = m & 1;
            float s = 0.f;
#pragma unroll
            for (int u = 0; u < 4; u++)
#pragma unroll
                for (int v2 = 0; v2 < 4; v2++)
                    s += a8[c * 64 + (qi * 4 + u) * 8 + qj * 4 + v2];
            cavg[tid] = s * (1.f / 16.f);
        }
        for (int eh = tid; eh < HIDM * 64; eh += 256) {
            int j = eh >> 6, p = eh & 63;
            float s = b1s[j];
#pragma unroll
            for (int c = 0; c < HDIM; c++) s += w1s[j * HDIM + c] * a8[c * 64 + p];
            hbuf[eh] = 0.5f * s * (1.f + erff(s * 0.70710678118654752440f));
        }
        __syncthreads();
        for (int eo = tid; eo < 2048; eo += 256) {
            int c = eo >> 6, p = eo & 63;
            float s = b2s[c];
#pragma unroll
            for (int j = 0; j < HIDM; j++) s += w2s[c * HIDM + j] * hbuf[j * 64 + p];
            a8[eo] = s;
        }
        __syncthreads();
        if (tid < 128) {
            int m = tid >> 5, c = tid & 31, qi = m >> 1, qj = m & 1;
            float mx = -INFINITY;
#pragma unroll
            for (int u = 0; u < 4; u++)
#pragma unroll
                for (int v2 = 0; v2 < 4; v2++)
                    mx = fmaxf(mx, a8[c * 64 + (qi * 4 + u) * 8 + qj * 4 + v2]);
            dst[tid] = cavg[tid] + mx;
        }
        __syncthreads();
    }

    if (tid < 4) {
        float s = 0.f;
#pragma unroll
        for (int c = 0; c < HDIM; c++) { float v = ctrs[tid * 32 + c]; s += v * v; }
        cnorm[tid] = fmaxf(sqrtf(s), 1e-12f);
    }
    __syncthreads();
    if (tid < 128) {
        g_cns[(size_t)bbk * 128 + tid] = ctrs[tid] / cnorm[tid >> 5];
        g_vcs[(size_t)bbk * 128 + tid] = vcs[tid];
    }
}

// ---------------- kernel 5: main fused GEMM (fc1) + sim/argmax epilogue ----------------
// 3-stage cp.async pipeline, single sync per iteration, 2 CTAs/SM.  (84.9us measured)
__global__ __launch_bounds__(256, 2)
void gemm_sim_kernel(const __half* __restrict__ whi, const __half* __restrict__ wlo,
                     const __half* __restrict__ xhi, const __half* __restrict__ xlo,
                     const float* __restrict__ alphaP, const float* __restrict__ betaP) {
    extern __shared__ __align__(1024) char sm[];   // 3 x 32KB stages; epilogue reuse
    __shared__ float cns_s[4][2][4][32];
    const int tid = threadIdx.x, lane = tid & 31, warp = tid >> 5;
    const int b = blockIdx.z, n0 = blockIdx.x * 128, m0 = blockIdx.y * 128;
    const int wm = (warp >> 2) * 64, wn = (warp & 3) * 32;

    const __half* srcs[4] = {
        whi + (size_t)m0 * DIMC, wlo + (size_t)m0 * DIMC,
        xhi + ((size_t)b * SPAT + n0) * DIMC, xlo + ((size_t)b * SPAT + n0) * DIMC };
    const uint32_t smb = smem_u32(sm);

    float acc[4][4][4];
#pragma unroll
    for (int i = 0; i < 4; i++)
#pragma unroll
        for (int j = 0; j < 4; j++)
#pragma unroll
            for (int k = 0; k < 4; k++) acc[i][j][k] = 0.f;

    auto load_stage = [&](int stage, int kc) {
#pragma unroll
        for (int t = 0; t < 4; t++) {
#pragma unroll
            for (int i = 0; i < 2; i++) {
                int chunkid = tid + 256 * i;
                int row = chunkid >> 2, c = chunkid & 3;
                cp_async16(smb + stage * 32768 + t * 8192 + sw_off(row, c),
                           srcs[t] + (size_t)row * DIMC + kc * 32 + c * 8);
            }
        }
        CP_COMMIT();
    };
    const int rl = lane & 7, sel = lane >> 3;

    load_stage(0, 0);
    load_stage(1, 1);
    for (int kc = 0; kc < 8; kc++) {
        if (kc < 7) { CP_WAIT(1); } else { CP_WAIT(0); }
        __syncthreads();
        if (kc + 2 < 8) load_stage((kc + 2) % 3, kc + 2);
        const uint32_t base = smb + (kc % 3) * 32768;
#pragma unroll
        for (int ks = 0; ks < 2; ks++) {
            uint32_t ahi[4][4], alo[4][4];
#pragma unroll
            for (int mt = 0; mt < 4; mt++) {
                int row = wm + mt * 16 + (sel & 1) * 8 + rl;
                int ch = ks * 2 + (sel >> 1);
                uint32_t o = sw_off(row, ch);
                ldsm4(ahi[mt], base + o);
                ldsm4(alo[mt], base + 8192 + o);
            }
            uint32_t bhi[4][2], blo[4][2];
#pragma unroll
            for (int p = 0; p < 2; p++) {
                int row = wn + p * 16 + (sel >> 1) * 8 + rl;
                int ch = ks * 2 + (sel & 1);
                uint32_t o = sw_off(row, ch);
                uint32_t r4[4];
                ldsm4(r4, base + 16384 + o);
                bhi[2 * p][0] = r4[0]; bhi[2 * p][1] = r4[1];
                bhi[2 * p + 1][0] = r4[2]; bhi[2 * p + 1][1] = r4[3];
                ldsm4(r4, base + 24576 + o);
                blo[2 * p][0] = r4[0]; blo[2 * p][1] = r4[1];
                blo[2 * p + 1][0] = r4[2]; blo[2 * p + 1][1] = r4[3];
            }
#pragma unroll
            for (int mt = 0; mt < 4; mt++)
#pragma unroll
                for (int nt = 0; nt < 4; nt++) {
                    mma_f16(acc[mt][nt], ahi[mt], bhi[nt]);
                    mma_f16(acc[mt][nt], ahi[mt], blo[nt]);
                    mma_f16(acc[mt][nt], alo[mt], bhi[nt]);
                }
        }
    }
    __syncthreads();    // all warps done with stage buffers before epilogue reuse

    const int h0 = m0 >> 5;
    const int fi = (n0 >= 2048) ? 1 : 0;
    float* epi = (float*)sm;                // [128 rows][132 stride]
    {
        const int g = lane >> 2, tig = lane & 3;
#pragma unroll
        for (int mt = 0; mt < 4; mt++) {
            int lr0 = wm + mt * 16 + g;
            float b0v = g_bb[b * 512 + m0 + lr0];
            float b1v = g_bb[b * 512 + m0 + lr0 + 8];
#pragma unroll
            for (int nt = 0; nt < 4; nt++) {
                int col = wn + nt * 8 + 2 * tig;
                epi[lr0 * 132 + col]           = acc[mt][nt][0] + b0v;
                epi[lr0 * 132 + col + 1]       = acc[mt][nt][1] + b0v;
                epi[(lr0 + 8) * 132 + col]     = acc[mt][nt][2] + b1v;
                epi[(lr0 + 8) * 132 + col + 1] = acc[mt][nt][3] + b1v;
            }
        }
    }
    for (int i = tid; i < 1024; i += 256) {
        int hl = i >> 8, fjj = (i >> 7) & 1, m = (i >> 5) & 3, d = i & 31;
        int bbk = b * 32 + (h0 + hl) * 4 + fi * 2 + fjj;
        cns_s[hl][fjj][m][d] = g_cns[(size_t)bbk * 128 + m * 32 + d];
    }
    __syncthreads();

    const float alpha = alphaP[0], beta = betaP[0];
    const int hl = tid >> 6, tp = tid & 63;
#pragma unroll
    for (int rep = 0; rep < 2; rep++) {
        int tk = tp * 2 + rep;
        int s = n0 + tk;
        int hj = s & 63, fj = hj >> 5;
        int nw = ((s >> 6) & 31) * 32 + (hj & 31);
        float nrm = 0.f, dm[4] = {0.f, 0.f, 0.f, 0.f};
#pragma unroll
        for (int d = 0; d < 32; d++) {
            float v = epi[(hl * 32 + d) * 132 + tk];
            nrm += v * v;
#pragma unroll
            for (int m = 0; m < 4; m++) dm[m] += cns_s[hl][fj][m][d] * v;
        }
        float inv = 1.f / fmaxf(sqrtf(nrm), 1e-12f);
        float best = -1.f; int bm = 0;
#pragma unroll
        for (int m = 0; m < 4; m++) {
            float sg = 1.f / (1.f + expf(-(beta + alpha * dm[m] * inv)));
            if (sg > best) { best = sg; bm = m; }
        }
        size_t idx = ((size_t)(b * 8 + h0 + hl) * 4 + fi * 2 + fj) * 1024 + nw;
        g_sim[idx] = best;
        g_mstar[idx] = (unsigned char)bm;
    }
}

// ---------------- kernel 6: t = sum sim*x  (grid: 4 cgroups x 4 win x B) ----------------
__global__ __launch_bounds__(256)
void taccum_kernel() {
    const int cg = blockIdx.x;
    const int win = blockIdx.y;
    const int b = blockIdx.z;
    const int fi = win >> 1, fj = win & 1;
    const int tid = threadIdx.x;
    const int cp = tid & 31;
    const int h = tid >> 5;

    __shared__ float stage[64][64];
    __shared__ float ws[8][4][64];

    float2 acc[4];
#pragma unroll
    for (int m = 0; m < 4; m++) acc[m] = make_float2(0.f, 0.f);

    for (int chunk = 0; chunk < 16; chunk++) {
#pragma unroll
        for (int it = 0; it < 8; it++) {
            int i = it * 256 + tid;
            int t = i >> 5, cq = i & 31;
            int n = chunk * 64 + t;
            int s = (fi * 32 + (n >> 5)) * 64 + fj * 32 + (n & 31);
            size_t off2 = (((size_t)b * SPAT + s) * DIMC + cg * 64) / 2 + cq;
            float2 hf = __half22float2(reinterpret_cast<const __half2*>(g_xthi)[off2]);
            float2 lf = __half22float2(reinterpret_cast<const __half2*>(g_xtlo)[off2]);
            *reinterpret_cast<float2*>(&stage[t][2 * cq]) =
                make_float2(hf.x + lf.x, hf.y + lf.y);
        }
#pragma unroll
        for (int it = 0; it < 8; it++) {
            int i = it * 256 + tid;
            int hh = i >> 8, mm = (i >> 6) & 3, t = i & 63;
            size_t sb = ((size_t)(b * 8 + hh) * 4 + win) * 1024 + chunk * 64 + t;
            ws[hh][mm][t] = (g_mstar[sb] == (unsigned char)mm) ? g_sim[sb] : 0.f;
        }
        __syncthreads();
#pragma unroll 4
        for (int t = 0; t < 64; t++) {
            float2 xv = *reinterpret_cast<const float2*>(&stage[t][2 * cp]);
#pragma unroll
            for (int m = 0; m < 4; m++) {
                float w = ws[h][m][t];
                acc[m].x += w * xv.x;
                acc[m].y += w * xv.y;
            }
        }
        __syncthreads();
    }
#pragma unroll
    for (int m = 0; m < 4; m++) {
        size_t o = (((size_t)(b * 4 + win) * 8 + h) * 4 + m) * 256 + cg * 64 + 2 * cp;
        *reinterpret_cast<float2*>(&g_t[o]) = acc[m];
    }
}

// ---------------- kernel 7: outm + y fused ----------------
__global__ __launch_bounds__(256)
void outm_y_kernel(const float* __restrict__ wv, const float* __restrict__ w2) {
    const int bbk = blockIdx.x;
    const int b = bbk >> 5;
    const int h = (bbk >> 2) & 7;
    const int win = bbk & 3;
    const int tid = threadIdx.x, lane = tid & 31, warp = tid >> 5;

    __shared__ float t_s[4][256];
    __shared__ float wbuf[8448];
    __shared__ float sigs[4], cnts[4];
    __shared__ float outm_s[128];

    for (int i = tid; i < 1024; i += 256)
        t_s[i >> 8][i & 255] = g_t[(((size_t)(b * 4 + win) * 8 + h) * 4 + (i >> 8)) * 256 + (i & 255)];
    if (warp < 4) {
        float s = 0.f, c = 0.f;
        for (int n = lane; n < 1024; n += 32) {
            size_t sb = ((size_t)(b * 8 + h) * 4 + win) * 1024 + n;
            if (g_mstar[sb] == (unsigned char)warp) { s += g_sim[sb]; c += 1.f; }
        }
        for (int o = 16; o; o >>= 1) {
            s += __shfl_down_sync(0xffffffffu, s, o);
            c += __shfl_down_sync(0xffffffffu, c, o);
        }
        if (lane == 0) { sigs[warp] = s; cnts[warp] = c; }
    }
    for (int i = tid; i < 32 * 256; i += 256) {
        int r = i >> 8, c = i & 255;
        wbuf[r * 257 + c] = wv[(size_t)(h * HDIM + r) * DIMC + c];
    }
    __syncthreads();

    if (tid < 128) {
        int m = tid >> 5, d = tid & 31;
        float s = 0.f;
#pragma unroll 8
        for (int c = 0; c < DIMC; c++) s += wbuf[d * 257 + c] * t_s[m][c];
        float bbv = g_bb[b * 512 + 256 + h * HDIM + d];
        float vc = g_vcs[(size_t)bbk * 128 + m * 32 + d];
        outm_s[tid] = (s + sigs[m] * bbv + vc) / (cnts[m] + 1.f);
    }
    __syncthreads();
    for (int i = tid; i < 256 * 32; i += 256) {
        int o = i >> 5, d = i & 31;
        wbuf[o * 33 + d] = w2[(size_t)o * DIMC + h * HDIM + d];
    }
    __syncthreads();
    {
        int o = tid;
        float yv[4] = {0.f, 0.f, 0.f, 0.f};
#pragma unroll
        for (int d = 0; d < HDIM; d++) {
            float w = wbuf[o * 33 + d];
#pragma unroll
            for (int m = 0; m < 4; m++) yv[m] += w * outm_s[m * 32 + d];
        }
#pragma unroll
        for (int m = 0; m < 4; m++)
            g_y[(size_t)bbk * 1024 + m * 256 + o] = yv[m];
    }
}

// ---------------- kernel 8: combine -> final output ----------------
__global__ __launch_bounds__(256)
void combine_kernel(const float* __restrict__ b2, float* __restrict__ out) {
    const int o0 = blockIdx.x * 32;
    const int win = blockIdx.y;
    const int batch = blockIdx.z;
    const int fi = win >> 1, fj = win & 1;
    const int tid = threadIdx.x, lane = tid & 31, warp = tid >> 5;

    __shared__ float ys[8][4][33];
    __shared__ float b2s[32];

    for (int i = tid; i < 8 * 4 * 32; i += 256) {
        int h = i >> 7, m = (i >> 5) & 3, o = i & 31;
        ys[h][m][o] = g_y[((size_t)(batch * 8 + h) * 4 + win) * 1024 + m * 256 + o0 + o];
    }
    if (tid < 32) b2s[tid] = b2[o0 + tid];
    __syncthreads();

#pragma unroll
    for (int r = 0; r < 4; r++) {
        int wi = warp * 4 + r;
        int n = wi * 32 + lane;
        float simr[8];
        int mr[8];
#pragma unroll
        for (int h = 0; h < 8; h++) {
            size_t sb = ((size_t)(batch * 8 + h) * 4 + win) * 1024 + n;
            simr[h] = g_sim[sb];
            mr[h] = g_mstar[sb];
        }
        int s = (fi * 32 + wi) * 64 + fj * 32 + lane;
        float* op = out + ((size_t)batch * DIMC + o0) * SPAT + s;
#pragma unroll
        for (int o = 0; o < 32; o++) {
            float acc = b2s[o];
#pragma unroll
            for (int h = 0; h < 8; h++) acc += simr[h] * ys[h][mr[h]][o];
            op[(size_t)o * SPAT] = acc;
        }
    }
}

// ---------------- launcher ----------------
extern "C" void kernel_launch(void* const* d_in, const int* in_sizes, int n_in,
                              void* d_out, int out_size) {
    const float* x      = (const float*)d_in[0];
    const float* scaler = (const float*)d_in[1];
    const float* w_fc1  = (const float*)d_in[2];
    const float* b_fc1  = (const float*)d_in[3];
    const float* w_fcv  = (const float*)d_in[4];
    const float* b_fcv  = (const float*)d_in[5];
    const float* w_fc2  = (const float*)d_in[6];
    const float* b_fc2  = (const float*)d_in[7];
    const float* alpha  = (const float*)d_in[8];
    const float* beta   = (const float*)d_in[9];
    const float* off_w1 = (const float*)d_in[10];
    const float* off_b1 = (const float*)d_in[11];
    const float* off_w2 = (const float*)d_in[12];
    const float* off_b2 = (const float*)d_in[13];
    float* out = (float*)d_out;

    int B = in_sizes[0] / (DIMC * SPAT);
    if (B > MAXB) B = MAXB;

    float *p_pool, *p_bb, *p_pxv;
    __half *p_w1h, *p_w1l, *p_xth, *p_xtl, *p_pth, *p_ptl;
    cudaGetSymbolAddress((void**)&p_pool, g_pool);
    cudaGetSymbolAddress((void**)&p_bb,   g_bb);
    cudaGetSymbolAddress((void**)&p_pxv,  g_pxv);
    cudaGetSymbolAddress((void**)&p_w1h,  g_w1hi);
    cudaGetSymbolAddress((void**)&p_w1l,  g_w1lo);
    cudaGetSymbolAddress((void**)&p_xth,  g_xthi);
    cudaGetSymbolAddress((void**)&p_xtl,  g_xtlo);
    cudaGetSymbolAddress((void**)&p_pth,  g_pthi);
    cudaGetSymbolAddress((void**)&p_ptl,  g_ptlo);

    static bool attr_set = false;
    if (!attr_set) {
        cudaFuncSetAttribute(gemm_hmma_kernel, cudaFuncAttributeMaxDynamicSharedMemorySize, 65536);
        cudaFuncSetAttribute(gemm_sim_kernel,  cudaFuncAttributeMaxDynamicSharedMemorySize, 98304);
        attr_set = true;
    }

    // 0. fused x reader: transpose+split + pooled
    {
        dim3 g(16, 8, B);
        convxp_kernel<<<g, 256>>>(x);
    }
    // 1. fused mean + adjusted bias + fp16 weight split
    biasmeanw_kernel<<<B + 512, 256>>>(w_fc1, b_fc1, w_fcv, b_fcv, scaler, B);
    // 2. pooled transpose+split
    {
        dim3 g(256 / 32, DIMC / 32, B);
        convx_kernel<<<g, dim3(32, 8)>>>(p_pool, p_pth, p_ptl, 256);
    }
    // 3. pooled conv (fc1+fcv on pooled x)
    {
        dim3 grid(256 / 128, 512 / 128, B);
        gemm_hmma_kernel<<<grid, 256, 65536>>>(p_w1h, p_w1l, p_pth, p_ptl, p_bb, p_pxv, 512, 256, 1);
    }
    // 4. centers + normalized cn + value centers (high-occupancy version)
    centers_kernel<<<B * 32, 256>>>(off_w1, off_b1, off_w2, off_b2);
    // 5. main fused GEMM + sim/argmax (84.9us measured, tensor 57.9%)
    {
        dim3 grid(SPAT / 128, 256 / 128, B);
        gemm_sim_kernel<<<grid, 256, 98304>>>(p_w1h, p_w1l, p_xth, p_xtl, alpha, beta);
    }
    // 6. t = sum sim*x per cluster
    {
        dim3 grid(4, 4, B);
        taccum_kernel<<<grid, 256>>>();
    }
    // 7. outm + y fused
    outm_y_kernel<<<B * 32, 256>>>(w_fcv, w_fc2);
    // 8. combine -> final output
    {
        dim3 grid(8, 4, B);
        combine_kernel<<<grid, 256>>>(b_fc2, out);
    }
}